// round 15
// baseline (speedup 1.0000x reference)
#include <cuda_runtime.h>

constexpr int B = 4, N = 512, HID = 256, H = 8, E = 32, DK = 32;
constexpr float SCALE = 0.17677669529663687f;   // 32^-0.5
constexpr float NEGV  = -9.0e15f;

typedef unsigned long long ull;

// ---------------- packed f32x2 helpers -------------------------------------
__device__ __forceinline__ ull pk2(float lo, float hi) {
    ull r; asm("mov.b64 %0, {%1, %2};" : "=l"(r) : "f"(lo), "f"(hi)); return r;
}
__device__ __forceinline__ ull dup2(float v) { return pk2(v, v); }
__device__ __forceinline__ void fma2(ull& d, ull a, ull b) {
    asm("fma.rn.f32x2 %0, %1, %2, %0;" : "+l"(d) : "l"(a), "l"(b));
}
__device__ __forceinline__ float2 up2(ull r) {
    float2 f; asm("mov.b64 {%0, %1}, %2;" : "=f"(f.x), "=f"(f.y) : "l"(r)); return f;
}

// ---------------- scratch (static device globals; no runtime allocation) ----
__device__ float gQKV[3*B*N*HID];         // Qh | Kh | Vh
__device__ float gX  [B*H*(size_t)N*N];   // x[b,h,i,j] post-mask
__device__ float gEB [B*H*(size_t)N*N];   // edge_bias2 in [b,h,i,j] layout
__device__ float gWt [B*H*(size_t)N*N];   // combined softmax weights [b,h,i,j]
__device__ float gAtt[B*N*HID];           // (x_local+x_long) flattened

// ============ GEMM: C[2048,256] = A @ W^T + bias ===========================
__device__ __forceinline__ void gemm_nt_body(
    const float* __restrict__ A, const float* __restrict__ W,
    const float* __restrict__ bias, float* __restrict__ C)
{
    constexpr int Kd = 256;
    __shared__ __align__(16) float As[16][68];
    __shared__ __align__(16) float Bs[16][68];
    const int l  = threadIdx.x;
    const int tx = l & 15, ty = l >> 4;
    const int m0 = blockIdx.y * 64, n0 = blockIdx.x * 64;
    const int lrow = l >> 2, lq = l & 3;
    ull acc2[4][2];
    #pragma unroll
    for (int i = 0; i < 4; i++) { acc2[i][0] = 0ull; acc2[i][1] = 0ull; }
    for (int k0 = 0; k0 < Kd; k0 += 16) {
        float4 a4 = *(const float4*)(A + (size_t)(m0 + lrow) * Kd + k0 + lq * 4);
        float4 b4 = *(const float4*)(W + (size_t)(n0 + lrow) * Kd + k0 + lq * 4);
        As[lq*4+0][lrow] = a4.x; As[lq*4+1][lrow] = a4.y;
        As[lq*4+2][lrow] = a4.z; As[lq*4+3][lrow] = a4.w;
        Bs[lq*4+0][lrow] = b4.x; Bs[lq*4+1][lrow] = b4.y;
        Bs[lq*4+2][lrow] = b4.z; Bs[lq*4+3][lrow] = b4.w;
        __syncthreads();
        #pragma unroll
        for (int k = 0; k < 16; k++) {
            float4 av = *(const float4*)&As[k][ty*4];
            ulonglong2 b2 = *(const ulonglong2*)&Bs[k][tx*4];
            ull a2[4] = {dup2(av.x), dup2(av.y), dup2(av.z), dup2(av.w)};
            #pragma unroll
            for (int ii = 0; ii < 4; ii++) {
                fma2(acc2[ii][0], a2[ii], b2.x);
                fma2(acc2[ii][1], a2[ii], b2.y);
            }
        }
        __syncthreads();
    }
    #pragma unroll
    for (int ii = 0; ii < 4; ii++) {
        int m = m0 + ty*4 + ii;
        float2 p0 = up2(acc2[ii][0]), p1 = up2(acc2[ii][1]);
        float4 o;
        o.x = p0.x + bias[n0 + tx*4 + 0];
        o.y = p0.y + bias[n0 + tx*4 + 1];
        o.z = p1.x + bias[n0 + tx*4 + 2];
        o.w = p1.y + bias[n0 + tx*4 + 3];
        *(float4*)(C + (size_t)m * 256 + n0 + tx*4) = o;
    }
}

__global__ __launch_bounds__(256) void gemm_one_kernel(
    int z, const float* A, const float* W, const float* bias)
{
    gemm_nt_body(A, W, bias, gQKV + (size_t)z * B * N * HID);
}

__global__ __launch_bounds__(256) void gemm_out_kernel(
    const float* __restrict__ Wo, const float* __restrict__ bo, float* __restrict__ out)
{
    gemm_nt_body(gAtt, Wo, bo, out);
}

// ============ x[b,h,i,j] = mask(SCALE * Qh Kh^T), 128x128 tiles ============
__global__ __launch_bounds__(256) void qk_kernel(const float* __restrict__ adj,
                                                 const int* __restrict__ use_adj)
{
    __shared__ __align__(16) float Qs[32][132];
    __shared__ __align__(16) float Ks[32][132];
    const int l  = threadIdx.x;
    const int bh = blockIdx.z, b = bh >> 3, h = bh & 7;
    const int i0 = blockIdx.y * 128, j0 = blockIdx.x * 128;
    const float* Qg = gQKV + (size_t)b * N * HID + h * DK;
    const float* Kg = gQKV + (size_t)B*N*HID + (size_t)b * N * HID + h * DK;
    #pragma unroll
    for (int it = 0; it < 4; it++) {
        int e = l + it * 256;
        int row = e >> 3, q4 = e & 7;
        float4 a4 = *(const float4*)(Qg + (size_t)(i0 + row) * HID + q4 * 4);
        float4 b4 = *(const float4*)(Kg + (size_t)(j0 + row) * HID + q4 * 4);
        Qs[q4*4+0][row] = a4.x; Qs[q4*4+1][row] = a4.y;
        Qs[q4*4+2][row] = a4.z; Qs[q4*4+3][row] = a4.w;
        Ks[q4*4+0][row] = b4.x; Ks[q4*4+1][row] = b4.y;
        Ks[q4*4+2][row] = b4.z; Ks[q4*4+3][row] = b4.w;
    }
    __syncthreads();
    const int tx = l & 15, ty = l >> 4;
    ull acc2[8][4];
    #pragma unroll
    for (int i = 0; i < 8; i++)
        #pragma unroll
        for (int j = 0; j < 4; j++) acc2[i][j] = 0ull;
    #pragma unroll
    for (int k = 0; k < 32; k++) {
        float4 t0 = *(const float4*)&Qs[k][ty*8];
        float4 t1 = *(const float4*)&Qs[k][ty*8+4];
        ull a2[8] = {dup2(t0.x), dup2(t0.y), dup2(t0.z), dup2(t0.w),
                     dup2(t1.x), dup2(t1.y), dup2(t1.z), dup2(t1.w)};
        ulonglong2 bq0 = *(const ulonglong2*)&Ks[k][tx*8];
        ulonglong2 bq1 = *(const ulonglong2*)&Ks[k][tx*8+4];
        ull b2[4] = {bq0.x, bq0.y, bq1.x, bq1.y};
        #pragma unroll
        for (int ii = 0; ii < 8; ii++)
            #pragma unroll
            for (int jj = 0; jj < 4; jj++)
                fma2(acc2[ii][jj], a2[ii], b2[jj]);
    }
    const int ua = use_adj[0];
    #pragma unroll
    for (int ii = 0; ii < 8; ii++) {
        int i = i0 + ty*8 + ii;
        const float* adjrow = adj + ((size_t)b * N + i) * N;
        float* xrow = gX + ((size_t)bh * N + i) * N;
        #pragma unroll
        for (int j4 = 0; j4 < 2; j4++) {
            int j = j0 + tx*8 + j4*4;
            float2 pa = up2(acc2[ii][j4*2+0]);
            float2 pb = up2(acc2[ii][j4*2+1]);
            float vv[4] = {pa.x * SCALE, pa.y * SCALE, pb.x * SCALE, pb.y * SCALE};
            if (ua) {
                #pragma unroll
                for (int jj = 0; jj < 4; jj++) {
                    float a = adjrow[j + jj];
                    vv[jj] = (a > 0.f ? vv[jj] : NEGV) * a;
                }
            }
            float4 o = {vv[0], vv[1], vv[2], vv[3]};
            *(float4*)(xrow + j) = o;
        }
    }
}

// ============ edge v9: 128 thr, 2 pairs/thr, shared Woe, staged store ======
__global__ __launch_bounds__(128) void edge_kernel(
    const float* __restrict__ edge_fea, const float* __restrict__ adj1,
    const float* __restrict__ Wap, const float* __restrict__ bap,
    const float* __restrict__ Wep, const float* __restrict__ bep,
    const float* __restrict__ Woe, float* __restrict__ edge_out)
{
    __shared__ __align__(16) float efs[16][514];   // 16p x (16q x 32e)
    __shared__ __align__(16) float WepTs[32][8];   // [e][h]  = Wep[h*32+e]
    __shared__ __align__(16) float WapTs[8][32];   // [h][e]  = Wap[e*8+h]
    __shared__ __align__(16) float WoeTs[32][32];  // [k][j]  = Woe[j*32+k]
    __shared__ __align__(16) float bapS[32];
    __shared__ float bepS[8];
    const int l = threadIdx.x;                     // 0..127
    const int b = blockIdx.z;
    const int p0 = blockIdx.y * 16, q0 = blockIdx.x * 16;

    #pragma unroll
    for (int t2 = 0; t2 < 2; t2++) {
        int idx = l + t2 * 128;
        WepTs[idx >> 3][idx & 7] = Wep[(idx & 7) * 32 + (idx >> 3)];
        WapTs[idx >> 5][idx & 31] = Wap[(idx & 31) * 8 + (idx >> 5)];
    }
    #pragma unroll
    for (int t8 = 0; t8 < 8; t8++) {
        int idx = l + t8 * 128;
        WoeTs[idx >> 5][idx & 31] = Woe[(idx & 31) * 32 + (idx >> 5)];
    }
    if (l < 32) bapS[l] = bap[l];
    if (l < 8)  bepS[l] = bep[l];

    // tile load: 16 rows x 512 floats; 8 threads/row, 16 float4 each
    const int lr = l >> 3, lc = l & 7;
    const float* efbase = edge_fea + (((size_t)b * N + p0 + lr) * N + q0) * E;
    #pragma unroll
    for (int k = 0; k < 16; k++) {
        int c4 = lc + k * 8;
        float4 v = *(const float4*)(efbase + c4 * 4);
        efs[lr][c4*4+0] = v.x; efs[lr][c4*4+1] = v.y;
        efs[lr][c4*4+2] = v.z; efs[lr][c4*4+3] = v.w;
    }
    __syncthreads();

    const int tp = l & 15, tq0 = l >> 4;   // tq0 in 0..7; pairs tq0, tq0+8
    const int p = p0 + tp;

    // ---- stages A+B per pair (own slots only) ------------------------------
    #pragma unroll
    for (int pr = 0; pr < 2; pr++) {
        const int tq = tq0 + pr * 8;
        const int q = q0 + tq;
        float* slot = &efs[tp][tq * 32];

        ull efp[16];
        #pragma unroll
        for (int e2 = 0; e2 < 16; e2++) efp[e2] = *(const ull*)(slot + 2*e2);

        float xh[8];
        #pragma unroll
        for (int hh = 0; hh < 8; hh++)
            xh[hh] = gX[(((size_t)b * H + hh) * N + q) * N + p];
        const float a1t = adj1[((size_t)b * N + q) * N + p];

        // Stage A: eb[h] = ef . Wep[h,:] + bep[h]
        ull accA[4] = {0ull, 0ull, 0ull, 0ull};
        #pragma unroll
        for (int e2 = 0; e2 < 16; e2++) {
            float2 ev = up2(efp[e2]);
            ull d0 = dup2(ev.x), d1 = dup2(ev.y);
            ulonglong2 w0a = *(const ulonglong2*)&WepTs[2*e2][0];
            ulonglong2 w0b = *(const ulonglong2*)&WepTs[2*e2][4];
            ulonglong2 w1a = *(const ulonglong2*)&WepTs[2*e2+1][0];
            ulonglong2 w1b = *(const ulonglong2*)&WepTs[2*e2+1][4];
            fma2(accA[0], d0, w0a.x); fma2(accA[1], d0, w0a.y);
            fma2(accA[2], d0, w0b.x); fma2(accA[3], d0, w0b.y);
            fma2(accA[0], d1, w1a.x); fma2(accA[1], d1, w1a.y);
            fma2(accA[2], d1, w1b.x); fma2(accA[3], d1, w1b.y);
        }
        {
            float2 r0 = up2(accA[0]), r1 = up2(accA[1]), r2 = up2(accA[2]), r3 = up2(accA[3]);
            float rr[8] = {r0.x + bepS[0], r0.y + bepS[1], r1.x + bepS[2], r1.y + bepS[3],
                           r2.x + bepS[4], r2.y + bepS[5], r3.x + bepS[6], r3.y + bepS[7]};
            #pragma unroll
            for (int hh = 0; hh < 8; hh++)
                gEB[(((size_t)b * H + hh) * N + q) * N + p] = rr[hh];
        }

        // Stage B: t = ef + a1 * (x . Wap^T + bap)
        {
            ull accB[16];
            const ull* bap2 = (const ull*)bapS;
            #pragma unroll
            for (int e2 = 0; e2 < 16; e2++) accB[e2] = bap2[e2];
            #pragma unroll
            for (int hh = 0; hh < 8; hh++) {
                ull xd = dup2(xh[hh]);
                #pragma unroll
                for (int e4 = 0; e4 < 8; e4++) {
                    ulonglong2 w = *(const ulonglong2*)&WapTs[hh][e4*4];
                    fma2(accB[2*e4],   xd, w.x);
                    fma2(accB[2*e4+1], xd, w.y);
                }
            }
            ull a1d = dup2(a1t);
            #pragma unroll
            for (int e2 = 0; e2 < 16; e2++) fma2(efp[e2], a1d, accB[e2]);
        }

        #pragma unroll
        for (int e2 = 0; e2 < 16; e2++) *(ull*)(slot + 2*e2) = efp[e2];
    }
    // no sync: stage C reads only this thread's own two slots

    // ---- Stage C: full-width accs for both pairs; Woe loads shared ---------
    {
        float* slot0 = &efs[tp][tq0 * 32];
        float* slot1 = &efs[tp][(tq0 + 8) * 32];
        ull acc0[16], acc1[16];
        #pragma unroll
        for (int j2 = 0; j2 < 16; j2++) { acc0[j2] = 0ull; acc1[j2] = 0ull; }
        #pragma unroll
        for (int k2 = 0; k2 < 16; k2++) {
            float2 v0 = up2(*(const ull*)(slot0 + 2*k2));
            float2 v1 = up2(*(const ull*)(slot1 + 2*k2));
            ull d00 = dup2(v0.x), d01 = dup2(v0.y);
            ull d10 = dup2(v1.x), d11 = dup2(v1.y);
            const float* r0 = WoeTs[2*k2];
            const float* r1 = WoeTs[2*k2+1];
            #pragma unroll
            for (int j4 = 0; j4 < 8; j4++) {
                ulonglong2 w0 = *(const ulonglong2*)(r0 + j4*4);
                ulonglong2 w1 = *(const ulonglong2*)(r1 + j4*4);
                fma2(acc0[2*j4],   d00, w0.x); fma2(acc0[2*j4+1], d00, w0.y);
                fma2(acc0[2*j4],   d01, w1.x); fma2(acc0[2*j4+1], d01, w1.y);
                fma2(acc1[2*j4],   d10, w0.x); fma2(acc1[2*j4+1], d10, w0.y);
                fma2(acc1[2*j4],   d11, w1.x); fma2(acc1[2*j4+1], d11, w1.y);
            }
        }
        #pragma unroll
        for (int j2 = 0; j2 < 16; j2++) {
            *(ull*)(slot0 + 2*j2) = acc0[j2];
            *(ull*)(slot1 + 2*j2) = acc1[j2];
        }
    }
    __syncthreads();

    // staged coalesced store: 16 rows x 512 floats
    float* eob = edge_out + (((size_t)b * N + p0 + lr) * N + q0) * E;
    #pragma unroll
    for (int k = 0; k < 16; k++) {
        int c4 = lc + k * 8;
        float4 v = {efs[lr][c4*4+0], efs[lr][c4*4+1], efs[lr][c4*4+2], efs[lr][c4*4+3]};
        *(float4*)(eob + c4 * 4) = v;
    }
}

// ============ combined softmax weights: one block per (b,i), warp = head ====
__global__ __launch_bounds__(256) void softmax_kernel(
    const float* __restrict__ attn_bias, const float* __restrict__ adj1)
{
    const int bi = blockIdx.x;
    const int b = bi >> 9, i = bi & 511;
    const int h = threadIdx.x >> 5, lane = threadIdx.x & 31;
    const size_t bh = (size_t)b * H + h;
    const float* xrow  = gX + (bh * N + i) * N;
    const float* abrow = attn_bias + (bh * N + i) * N;
    const float* ebrow = gEB + (bh * N + i) * N;
    const float* a1row = adj1 + (size_t)bi * N;

    float lgG[16], lgL[16];
    float mG = -3.4e38f, mL = -3.4e38f;
    #pragma unroll
    for (int k = 0; k < 16; k++) {
        int j = lane + k * 32;
        float xv = xrow[j];
        float g  = xv * abrow[j];
        float ll = xv * ebrow[j] * a1row[j];
        lgG[k] = g; lgL[k] = ll;
        mG = fmaxf(mG, g); mL = fmaxf(mL, ll);
    }
    #pragma unroll
    for (int o = 16; o > 0; o >>= 1) {
        mG = fmaxf(mG, __shfl_xor_sync(0xffffffffu, mG, o));
        mL = fmaxf(mL, __shfl_xor_sync(0xffffffffu, mL, o));
    }
    float sG = 0.f, sL = 0.f;
    #pragma unroll
    for (int k = 0; k < 16; k++) {
        float eG = __expf(lgG[k] - mG);
        float eL = __expf(lgL[k] - mL);
        lgG[k] = eG; lgL[k] = eL;
        sG += eG; sL += eL;
    }
    #pragma unroll
    for (int o = 16; o > 0; o >>= 1) {
        sG += __shfl_xor_sync(0xffffffffu, sG, o);
        sL += __shfl_xor_sync(0xffffffffu, sL, o);
    }
    const float iG = 1.f / sG, iL = 1.f / sL;
    float* wrow = gWt + (bh * N + i) * N;
    #pragma unroll
    for (int k = 0; k < 16; k++)
        wrow[lane + k * 32] = lgG[k] * iG + lgL[k] * iL;
}

// ============ AV: gAtt[b,i,h*32+d] = sum_j gWt[b,h,i,j] * Vh[b,j,h*32+d] ====
__global__ __launch_bounds__(256) void av_kernel()
{
    __shared__ __align__(16) float Ws[32][132];
    __shared__ __align__(16) float Vs[32][36];
    const int l = threadIdx.x;
    const int bh = blockIdx.y, b = bh >> 3, h = bh & 7;
    const int i0 = blockIdx.x * 128;
    const float* Wg = gWt + ((size_t)bh * N + i0) * N;
    const float* Vg = gQKV + 2*(size_t)B*N*HID + (size_t)b * N * HID + h * DK;
    const int tx = l & 15, ty = l >> 4;
    ull acc2[4][2];
    #pragma unroll
    for (int i = 0; i < 4; i++) { acc2[i][0] = 0ull; acc2[i][1] = 0ull; }
    for (int k0 = 0; k0 < N; k0 += 32) {
        #pragma unroll
        for (int it = 0; it < 4; it++) {
            int e = l + it * 256;
            int row = e >> 3, q4 = e & 7;
            float4 v = *(const float4*)(Wg + (size_t)row * N + k0 + q4 * 4);
            Ws[q4*4+0][row] = v.x; Ws[q4*4+1][row] = v.y;
            Ws[q4*4+2][row] = v.z; Ws[q4*4+3][row] = v.w;
        }
        {
            int row = l >> 3, q4 = l & 7;
            float4 v = *(const float4*)(Vg + (size_t)(k0 + row) * HID + q4 * 4);
            *(float4*)&Vs[row][q4*4] = v;
        }
        __syncthreads();
        #pragma unroll
        for (int kk = 0; kk < 32; kk++) {
            ulonglong2 aa0 = *(const ulonglong2*)&Ws[kk][ty*8];
            ulonglong2 aa1 = *(const ulonglong2*)&Ws[kk][ty*8+4];
            ull a2[4] = {aa0.x, aa0.y, aa1.x, aa1.y};
            float2 bv = *(const float2*)&Vs[kk][tx*2];
            ull bx = dup2(bv.x), by = dup2(bv.y);
            #pragma unroll
            for (int rp = 0; rp < 4; rp++) {
                fma2(acc2[rp][0], a2[rp], bx);
                fma2(acc2[rp][1], a2[rp], by);
            }
        }
        __syncthreads();
    }
    #pragma unroll
    for (int rp = 0; rp < 4; rp++) {
        float2 c0 = up2(acc2[rp][0]);
        float2 c1 = up2(acc2[rp][1]);
        float2 o0 = {c0.x, c1.x};
        float2 o1 = {c0.y, c1.y};
        *(float2*)(gAtt + ((size_t)b * N + i0 + ty*8 + 2*rp    ) * HID + h * DK + tx * 2) = o0;
        *(float2*)(gAtt + ((size_t)b * N + i0 + ty*8 + 2*rp + 1) * HID + h * DK + tx * 2) = o1;
    }
}

// ===========================================================================
extern "C" void kernel_launch(void* const* d_in, const int* in_sizes, int n_in,
                              void* d_out, int out_size)
{
    (void)in_sizes; (void)n_in; (void)out_size;
    const float* q         = (const float*)d_in[0];
    const float* k         = (const float*)d_in[1];
    const float* v         = (const float*)d_in[2];
    const float* adj       = (const float*)d_in[3];
    const float* adj1      = (const float*)d_in[4];
    const float* edge_fea  = (const float*)d_in[5];
    const float* attn_bias = (const float*)d_in[6];
    const float* Wq = (const float*)d_in[7];
    const float* bq = (const float*)d_in[8];
    const float* Wk = (const float*)d_in[9];
    const float* bk = (const float*)d_in[10];
    const float* Wv = (const float*)d_in[11];
    const float* bv = (const float*)d_in[12];
    const float* Wap = (const float*)d_in[13];
    const float* bap = (const float*)d_in[14];
    const float* Wep = (const float*)d_in[15];
    const float* bep = (const float*)d_in[16];
    const float* Wo  = (const float*)d_in[17];
    const float* bo  = (const float*)d_in[18];
    const float* Woe = (const float*)d_in[19];
    const int* use_adj = (const int*)d_in[20];

    float* out      = (float*)d_out;
    float* edge_out = out + (size_t)B * N * HID;

    // edge_kernel is the 4th launch (ncu profiles #4); deps respected.
    gemm_one_kernel<<<dim3(4, 32), 256>>>(0, q, Wq, bq);
    gemm_one_kernel<<<dim3(4, 32), 256>>>(1, k, Wk, bk);
    qk_kernel<<<dim3(4, 4, B * H), 256>>>(adj, use_adj);
    edge_kernel<<<dim3(N / 16, N / 16, B), 128>>>(edge_fea, adj1, Wap, bap,
                                                  Wep, bep, Woe, edge_out);
    gemm_one_kernel<<<dim3(4, 32), 256>>>(2, v, Wv, bv);
    softmax_kernel<<<B * N, 256>>>(attn_bias, adj1);
    av_kernel<<<dim3(N / 128, B * H), 256>>>();
    gemm_out_kernel<<<dim3(4, 32), 256>>>(Wo, bo, out);
}

// round 16
// speedup vs baseline: 1.1353x; 1.1353x over previous
#include <cuda_runtime.h>

constexpr int B = 4, N = 512, HID = 256, H = 8, E = 32, DK = 32;
constexpr float SCALE = 0.17677669529663687f;   // 32^-0.5
constexpr float NEGV  = -9.0e15f;

typedef unsigned long long ull;

// ---------------- packed f32x2 helpers -------------------------------------
__device__ __forceinline__ ull pk2(float lo, float hi) {
    ull r; asm("mov.b64 %0, {%1, %2};" : "=l"(r) : "f"(lo), "f"(hi)); return r;
}
__device__ __forceinline__ ull dup2(float v) { return pk2(v, v); }
__device__ __forceinline__ void fma2(ull& d, ull a, ull b) {
    asm("fma.rn.f32x2 %0, %1, %2, %0;" : "+l"(d) : "l"(a), "l"(b));
}
__device__ __forceinline__ float2 up2(ull r) {
    float2 f; asm("mov.b64 {%0, %1}, %2;" : "=f"(f.x), "=f"(f.y) : "l"(r)); return f;
}

// ---------------- scratch (static device globals; no runtime allocation) ----
__device__ float gQKV[3*B*N*HID];         // Qh | Kh | Vh
__device__ float gX  [B*H*(size_t)N*N];   // x[b,h,i,j] post-mask
__device__ float gEB [B*(size_t)N*N*H];   // edge_bias2[b,i,j,h] = proj[b,j,i,h]
__device__ float gWt [B*H*(size_t)N*N];   // combined softmax weights [b,h,i,j]
__device__ float gAtt[B*N*HID];           // (x_local+x_long) flattened

// ============ GEMM body: C[2048,256] = A @ W^T + bias ======================
__device__ __forceinline__ void gemm_nt_body(
    const float* __restrict__ A, const float* __restrict__ W,
    const float* __restrict__ bias, float* __restrict__ C)
{
    constexpr int Kd = 256;
    __shared__ __align__(16) float As[16][68];
    __shared__ __align__(16) float Bs[16][68];
    const int l  = threadIdx.x;
    const int tx = l & 15, ty = l >> 4;
    const int m0 = blockIdx.y * 64, n0 = blockIdx.x * 64;
    const int lrow = l >> 2, lq = l & 3;
    ull acc2[4][2];
    #pragma unroll
    for (int i = 0; i < 4; i++) { acc2[i][0] = 0ull; acc2[i][1] = 0ull; }
    for (int k0 = 0; k0 < Kd; k0 += 16) {
        float4 a4 = *(const float4*)(A + (size_t)(m0 + lrow) * Kd + k0 + lq * 4);
        float4 b4 = *(const float4*)(W + (size_t)(n0 + lrow) * Kd + k0 + lq * 4);
        As[lq*4+0][lrow] = a4.x; As[lq*4+1][lrow] = a4.y;
        As[lq*4+2][lrow] = a4.z; As[lq*4+3][lrow] = a4.w;
        Bs[lq*4+0][lrow] = b4.x; Bs[lq*4+1][lrow] = b4.y;
        Bs[lq*4+2][lrow] = b4.z; Bs[lq*4+3][lrow] = b4.w;
        __syncthreads();
        #pragma unroll
        for (int k = 0; k < 16; k++) {
            float4 av = *(const float4*)&As[k][ty*4];
            ull b2[2];
            b2[0] = *(const ull*)&Bs[k][tx*4];
            b2[1] = *(const ull*)&Bs[k][tx*4+2];
            ull a2[4] = {dup2(av.x), dup2(av.y), dup2(av.z), dup2(av.w)};
            #pragma unroll
            for (int ii = 0; ii < 4; ii++) {
                fma2(acc2[ii][0], a2[ii], b2[0]);
                fma2(acc2[ii][1], a2[ii], b2[1]);
            }
        }
        __syncthreads();
    }
    #pragma unroll
    for (int ii = 0; ii < 4; ii++) {
        int m = m0 + ty*4 + ii;
        float2 p0 = up2(acc2[ii][0]), p1 = up2(acc2[ii][1]);
        float4 o;
        o.x = p0.x + bias[n0 + tx*4 + 0];
        o.y = p0.y + bias[n0 + tx*4 + 1];
        o.z = p1.x + bias[n0 + tx*4 + 2];
        o.w = p1.y + bias[n0 + tx*4 + 3];
        *(float4*)(C + (size_t)m * 256 + n0 + tx*4) = o;
    }
}

__global__ __launch_bounds__(256) void gemm_qkv_kernel(
    const float* q, const float* k, const float* v,
    const float* Wq, const float* Wk, const float* Wv,
    const float* bq, const float* bk, const float* bv)
{
    const int z = blockIdx.z;
    const float* A = (z == 0) ? q : (z == 1) ? k : v;
    const float* W = (z == 0) ? Wq : (z == 1) ? Wk : Wv;
    const float* bias = (z == 0) ? bq : (z == 1) ? bk : bv;
    gemm_nt_body(A, W, bias, gQKV + (size_t)z * B * N * HID);
}

__global__ __launch_bounds__(256) void gemm_out_kernel(
    const float* __restrict__ Wo, const float* __restrict__ bo, float* __restrict__ out)
{
    gemm_nt_body(gAtt, Wo, bo, out);
}

// ============ x[b,h,i,j] = mask(SCALE * Qh Kh^T) ===========================
__global__ __launch_bounds__(256) void qk_kernel(const float* __restrict__ adj,
                                                 const int* __restrict__ use_adj)
{
    __shared__ __align__(16) float Qs[32][132];
    __shared__ __align__(16) float Ks[32][132];
    const int l  = threadIdx.x;
    const int bh = blockIdx.z, b = bh >> 3, h = bh & 7;
    const int i0 = blockIdx.y * 128, j0 = blockIdx.x * 128;
    const float* Qg = gQKV + (size_t)b * N * HID + h * DK;
    const float* Kg = gQKV + (size_t)B*N*HID + (size_t)b * N * HID + h * DK;
    #pragma unroll
    for (int it = 0; it < 4; it++) {
        int e = l + it * 256;
        int row = e >> 3, q4 = e & 7;
        float4 a4 = *(const float4*)(Qg + (size_t)(i0 + row) * HID + q4 * 4);
        float4 b4 = *(const float4*)(Kg + (size_t)(j0 + row) * HID + q4 * 4);
        Qs[q4*4+0][row] = a4.x; Qs[q4*4+1][row] = a4.y;
        Qs[q4*4+2][row] = a4.z; Qs[q4*4+3][row] = a4.w;
        Ks[q4*4+0][row] = b4.x; Ks[q4*4+1][row] = b4.y;
        Ks[q4*4+2][row] = b4.z; Ks[q4*4+3][row] = b4.w;
    }
    __syncthreads();
    const int tx = l & 15, ty = l >> 4;
    ull acc2[8][4];
    #pragma unroll
    for (int i = 0; i < 8; i++)
        #pragma unroll
        for (int j = 0; j < 4; j++) acc2[i][j] = 0ull;
    #pragma unroll
    for (int k = 0; k < 32; k++) {
        float4 t0 = *(const float4*)&Qs[k][ty*8];
        float4 t1 = *(const float4*)&Qs[k][ty*8+4];
        ull a2[8] = {dup2(t0.x), dup2(t0.y), dup2(t0.z), dup2(t0.w),
                     dup2(t1.x), dup2(t1.y), dup2(t1.z), dup2(t1.w)};
        ull b2[4];
        b2[0] = *(const ull*)&Ks[k][tx*8+0];
        b2[1] = *(const ull*)&Ks[k][tx*8+2];
        b2[2] = *(const ull*)&Ks[k][tx*8+4];
        b2[3] = *(const ull*)&Ks[k][tx*8+6];
        #pragma unroll
        for (int ii = 0; ii < 8; ii++)
            #pragma unroll
            for (int jj = 0; jj < 4; jj++)
                fma2(acc2[ii][jj], a2[ii], b2[jj]);
    }
    const int ua = use_adj[0];
    #pragma unroll
    for (int ii = 0; ii < 8; ii++) {
        int i = i0 + ty*8 + ii;
        const float* adjrow = adj + ((size_t)b * N + i) * N;
        float* xrow = gX + ((size_t)bh * N + i) * N;
        #pragma unroll
        for (int j4 = 0; j4 < 2; j4++) {
            int j = j0 + tx*8 + j4*4;
            float2 pa = up2(acc2[ii][j4*2+0]);
            float2 pb = up2(acc2[ii][j4*2+1]);
            float vv[4] = {pa.x * SCALE, pa.y * SCALE, pb.x * SCALE, pb.y * SCALE};
            if (ua) {
                #pragma unroll
                for (int jj = 0; jj < 4; jj++) {
                    float a = adjrow[j + jj];
                    vv[jj] = (a > 0.f ? vv[jj] : NEGV) * a;
                }
            }
            float4 o = {vv[0], vv[1], vv[2], vv[3]};
            *(float4*)(xrow + j) = o;
        }
    }
}

// ============ fused edge kernel v2: independent accumulators ================
__global__ __launch_bounds__(256) void edge_kernel(
    const float* __restrict__ edge_fea, const float* __restrict__ adj1,
    const float* __restrict__ Wap, const float* __restrict__ bap,
    const float* __restrict__ Wep, const float* __restrict__ bep,
    const float* __restrict__ Woe, float* __restrict__ edge_out)
{
    __shared__ __align__(16) float efs[16][514];   // 16 p-rows x (16 q * 32 e)
    __shared__ __align__(16) float WepTs[32][8];   // [e][h]  = Wep[h*32+e]
    __shared__ __align__(16) float WapTs[8][32];   // [h][e]  = Wap[e*8+h]
    __shared__ __align__(16) float WoeTs[32][32];  // [k][j]  = Woe[j*32+k]
    __shared__ __align__(16) float bapS[32];
    __shared__ float bepS[8];
    const int l = threadIdx.x;
    const int b = blockIdx.z;
    const int p0 = blockIdx.y * 16, q0 = blockIdx.x * 16;

    { int e = l >> 3, h = l & 7;  WepTs[e][h] = Wep[h*32+e]; }
    { int h = l >> 5, e = l & 31; WapTs[h][e] = Wap[e*8+h];  }
    #pragma unroll
    for (int t4 = 0; t4 < 4; t4++) {
        int idx = l + t4 * 256;
        int kk = idx >> 5, j = idx & 31;
        WoeTs[kk][j] = Woe[j*32+kk];
    }
    if (l < 32) bapS[l] = bap[l];
    if (l < 8)  bepS[l] = bep[l];

    const int lr = l >> 4, lc = l & 15;
    const float* efbase = edge_fea + (((size_t)b * N + p0 + lr) * N + q0) * E;
    #pragma unroll
    for (int k = 0; k < 8; k++) {
        int c4 = lc + k * 16;
        float4 v = *(const float4*)(efbase + c4 * 4);
        efs[lr][c4*4+0] = v.x; efs[lr][c4*4+1] = v.y;
        efs[lr][c4*4+2] = v.z; efs[lr][c4*4+3] = v.w;
    }
    __syncthreads();

    const int tp = l & 15, tq = l >> 4;
    const int p = p0 + tp, q = q0 + tq;

    // ef for this position, packed (stride 514 is even -> 8B aligned)
    ull efp[16];
    #pragma unroll
    for (int e2 = 0; e2 < 16; e2++) efp[e2] = *(const ull*)&efs[tp][tq*32 + 2*e2];

    float xh[8];
    #pragma unroll
    for (int hh = 0; hh < 8; hh++)
        xh[hh] = gX[(((size_t)b * H + hh) * N + q) * N + p];
    const float a1t = adj1[((size_t)b * N + q) * N + p];

    // ---- Stage A: gEB[b,q,p,h] = ef . Wep[h,:] + bep[h] (4 indep packed accs)
    ull accA[4] = {0ull, 0ull, 0ull, 0ull};
    #pragma unroll
    for (int e2 = 0; e2 < 16; e2++) {
        float2 ev = up2(efp[e2]);
        ull d0 = dup2(ev.x), d1 = dup2(ev.y);
        const ull* w0 = (const ull*)WepTs[2*e2];
        const ull* w1 = (const ull*)WepTs[2*e2+1];
        #pragma unroll
        for (int h2 = 0; h2 < 4; h2++) { fma2(accA[h2], d0, w0[h2]); fma2(accA[h2], d1, w1[h2]); }
    }
    {
        float* ebout = gEB + (((size_t)b * N + q) * N + p) * H;
        float2 r0 = up2(accA[0]), r1 = up2(accA[1]), r2 = up2(accA[2]), r3 = up2(accA[3]);
        float4 o0 = {r0.x + bepS[0], r0.y + bepS[1], r1.x + bepS[2], r1.y + bepS[3]};
        float4 o1 = {r2.x + bepS[4], r2.y + bepS[5], r3.x + bepS[6], r3.y + bepS[7]};
        *(float4*)(ebout)     = o0;
        *(float4*)(ebout + 4) = o1;
    }

    // ---- Stage B: accB[e] = x[b,:,q,p] . Wap[e,:]  (16 indep packed accs)
    ull accB[16];
    #pragma unroll
    for (int e2 = 0; e2 < 16; e2++) accB[e2] = 0ull;
    #pragma unroll
    for (int hh = 0; hh < 8; hh++) {
        ull xd = dup2(xh[hh]);
        const ull* wp = (const ull*)WapTs[hh];
        #pragma unroll
        for (int e2 = 0; e2 < 16; e2++) fma2(accB[e2], xd, wp[e2]);
    }
    // t = ef + a1 * (accB + bap)   (stays packed, overwrites efp)
    {
        ull a1d = dup2(a1t);
        const ull* bap2 = (const ull*)bapS;
        #pragma unroll
        for (int e2 = 0; e2 < 16; e2++) {
            fma2(efp[e2], a1d, bap2[e2]);
            fma2(efp[e2], a1d, accB[e2]);
        }
    }

    // ---- Stage C: out[j] = t . Woe[j,:]  (16 indep packed accs)
    ull accC[16];
    #pragma unroll
    for (int j2 = 0; j2 < 16; j2++) accC[j2] = 0ull;
    #pragma unroll
    for (int k2 = 0; k2 < 16; k2++) {
        float2 tv = up2(efp[k2]);
        ull d0 = dup2(tv.x), d1 = dup2(tv.y);
        const ull* w0 = (const ull*)WoeTs[2*k2];
        const ull* w1 = (const ull*)WoeTs[2*k2+1];
        #pragma unroll
        for (int j2 = 0; j2 < 16; j2++) { fma2(accC[j2], d0, w0[j2]); fma2(accC[j2], d1, w1[j2]); }
    }
    __syncthreads();
    #pragma unroll
    for (int j2 = 0; j2 < 16; j2++)
        *(ull*)&efs[tp][tq*32 + 2*j2] = accC[j2];
    __syncthreads();
    float* eob = edge_out + (((size_t)b * N + p0 + lr) * N + q0) * E;
    #pragma unroll
    for (int k = 0; k < 8; k++) {
        int c4 = lc + k * 16;
        float4 v = {efs[lr][c4*4+0], efs[lr][c4*4+1], efs[lr][c4*4+2], efs[lr][c4*4+3]};
        *(float4*)(eob + c4 * 4) = v;
    }
}

// ============ combined softmax weights: one block per (b,i), warp = head ====
__global__ __launch_bounds__(256) void softmax_kernel(
    const float* __restrict__ attn_bias, const float* __restrict__ adj1)
{
    const int bi = blockIdx.x;
    const int b = bi >> 9, i = bi & 511;
    const int h = threadIdx.x >> 5, lane = threadIdx.x & 31;
    const size_t bh = (size_t)b * H + h;
    const float* xrow  = gX + (bh * N + i) * N;
    const float* abrow = attn_bias + (bh * N + i) * N;
    const float* ebrow = gEB + (size_t)bi * N * H + h;
    const float* a1row = adj1 + (size_t)bi * N;

    float lgG[16], lgL[16];
    float mG = -3.4e38f, mL = -3.4e38f;
    #pragma unroll
    for (int k = 0; k < 16; k++) {
        int j = lane + k * 32;
        float xv = xrow[j];
        float g  = xv * abrow[j];
        float ll = xv * ebrow[(size_t)j * H] * a1row[j];
        lgG[k] = g; lgL[k] = ll;
        mG = fmaxf(mG, g); mL = fmaxf(mL, ll);
    }
    #pragma unroll
    for (int o = 16; o > 0; o >>= 1) {
        mG = fmaxf(mG, __shfl_xor_sync(0xffffffffu, mG, o));
        mL = fmaxf(mL, __shfl_xor_sync(0xffffffffu, mL, o));
    }
    float sG = 0.f, sL = 0.f;
    #pragma unroll
    for (int k = 0; k < 16; k++) {
        float eG = __expf(lgG[k] - mG);
        float eL = __expf(lgL[k] - mL);
        lgG[k] = eG; lgL[k] = eL;
        sG += eG; sL += eL;
    }
    #pragma unroll
    for (int o = 16; o > 0; o >>= 1) {
        sG += __shfl_xor_sync(0xffffffffu, sG, o);
        sL += __shfl_xor_sync(0xffffffffu, sL, o);
    }
    const float iG = 1.f / sG, iL = 1.f / sL;
    float* wrow = gWt + (bh * N + i) * N;
    #pragma unroll
    for (int k = 0; k < 16; k++)
        wrow[lane + k * 32] = lgG[k] * iG + lgL[k] * iL;
}

// ============ AV: gAtt[b,i,h*32+d] = sum_j gWt[b,h,i,j] * Vh[b,j,h*32+d] ====
__global__ __launch_bounds__(256) void av_kernel()
{
    __shared__ __align__(16) float Ws[32][132];
    __shared__ __align__(16) float Vs[32][36];
    const int l = threadIdx.x;
    const int bh = blockIdx.y, b = bh >> 3, h = bh & 7;
    const int i0 = blockIdx.x * 128;
    const float* Wg = gWt + ((size_t)bh * N + i0) * N;
    const float* Vg = gQKV + 2*(size_t)B*N*HID + (size_t)b * N * HID + h * DK;
    const int tx = l & 15, ty = l >> 4;
    ull acc2[4][2];
    #pragma unroll
    for (int i = 0; i < 4; i++) { acc2[i][0] = 0ull; acc2[i][1] = 0ull; }
    for (int k0 = 0; k0 < N; k0 += 32) {
        #pragma unroll
        for (int it = 0; it < 4; it++) {
            int e = l + it * 256;
            int row = e >> 3, q4 = e & 7;
            float4 v = *(const float4*)(Wg + (size_t)row * N + k0 + q4 * 4);
            Ws[q4*4+0][row] = v.x; Ws[q4*4+1][row] = v.y;
            Ws[q4*4+2][row] = v.z; Ws[q4*4+3][row] = v.w;
        }
        {
            int row = l >> 3, q4 = l & 7;
            float4 v = *(const float4*)(Vg + (size_t)(k0 + row) * HID + q4 * 4);
            *(float4*)&Vs[row][q4*4] = v;
        }
        __syncthreads();
        #pragma unroll
        for (int kk = 0; kk < 32; kk++) {
            ull a2[4];
            a2[0] = *(const ull*)&Ws[kk][ty*8+0];
            a2[1] = *(const ull*)&Ws[kk][ty*8+2];
            a2[2] = *(const ull*)&Ws[kk][ty*8+4];
            a2[3] = *(const ull*)&Ws[kk][ty*8+6];
            float2 bv = *(const float2*)&Vs[kk][tx*2];
            ull bx = dup2(bv.x), by = dup2(bv.y);
            #pragma unroll
            for (int rp = 0; rp < 4; rp++) {
                fma2(acc2[rp][0], a2[rp], bx);
                fma2(acc2[rp][1], a2[rp], by);
            }
        }
        __syncthreads();
    }
    #pragma unroll
    for (int rp = 0; rp < 4; rp++) {
        float2 c0 = up2(acc2[rp][0]);
        float2 c1 = up2(acc2[rp][1]);
        float2 o0 = {c0.x, c1.x};
        float2 o1 = {c0.y, c1.y};
        *(float2*)(gAtt + ((size_t)b * N + i0 + ty*8 + 2*rp    ) * HID + h * DK + tx * 2) = o0;
        *(float2*)(gAtt + ((size_t)b * N + i0 + ty*8 + 2*rp + 1) * HID + h * DK + tx * 2) = o1;
    }
}

// ===========================================================================
extern "C" void kernel_launch(void* const* d_in, const int* in_sizes, int n_in,
                              void* d_out, int out_size)
{
    (void)in_sizes; (void)n_in; (void)out_size;
    const float* q         = (const float*)d_in[0];
    const float* k         = (const float*)d_in[1];
    const float* v         = (const float*)d_in[2];
    const float* adj       = (const float*)d_in[3];
    const float* adj1      = (const float*)d_in[4];
    const float* edge_fea  = (const float*)d_in[5];
    const float* attn_bias = (const float*)d_in[6];
    const float* Wq = (const float*)d_in[7];
    const float* bq = (const float*)d_in[8];
    const float* Wk = (const float*)d_in[9];
    const float* bk = (const float*)d_in[10];
    const float* Wv = (const float*)d_in[11];
    const float* bv = (const float*)d_in[12];
    const float* Wap = (const float*)d_in[13];
    const float* bap = (const float*)d_in[14];
    const float* Wep = (const float*)d_in[15];
    const float* bep = (const float*)d_in[16];
    const float* Wo  = (const float*)d_in[17];
    const float* bo  = (const float*)d_in[18];
    const float* Woe = (const float*)d_in[19];
    const int* use_adj = (const int*)d_in[20];

    float* out      = (float*)d_out;
    float* edge_out = out + (size_t)B * N * HID;

    gemm_qkv_kernel<<<dim3(4, 32, 3), 256>>>(q, k, v, Wq, Wk, Wv, bq, bk, bv);
    qk_kernel<<<dim3(4, 4, B * H), 256>>>(adj, use_adj);
    edge_kernel<<<dim3(N / 16, N / 16, B), 256>>>(edge_fea, adj1, Wap, bap,
                                                  Wep, bep, Woe, edge_out);
    softmax_kernel<<<B * N, 256>>>(attn_bias, adj1);
    av_kernel<<<dim3(N / 128, B * H), 256>>>();
    gemm_out_kernel<<<dim3(4, 32), 256>>>(Wo, bo, out);
}

// round 17
// speedup vs baseline: 1.1894x; 1.0476x over previous
#include <cuda_runtime.h>

constexpr int B = 4, N = 512, HID = 256, H = 8, E = 32, DK = 32;
constexpr float SCALE = 0.17677669529663687f;   // 32^-0.5
constexpr float NEGV  = -9.0e15f;

typedef unsigned long long ull;

// ---------------- packed f32x2 helpers -------------------------------------
__device__ __forceinline__ ull pk2(float lo, float hi) {
    ull r; asm("mov.b64 %0, {%1, %2};" : "=l"(r) : "f"(lo), "f"(hi)); return r;
}
__device__ __forceinline__ ull dup2(float v) { return pk2(v, v); }
__device__ __forceinline__ void fma2(ull& d, ull a, ull b) {
    asm("fma.rn.f32x2 %0, %1, %2, %0;" : "+l"(d) : "l"(a), "l"(b));
}
__device__ __forceinline__ float2 up2(ull r) {
    float2 f; asm("mov.b64 {%0, %1}, %2;" : "=f"(f.x), "=f"(f.y) : "l"(r)); return f;
}
// ---------------- tf32 helpers ---------------------------------------------
__device__ __forceinline__ float tf32r(float x) {
    unsigned u; asm("cvt.rna.tf32.f32 %0, %1;" : "=r"(u) : "f"(x));
    return __uint_as_float(u);
}
__device__ __forceinline__ void mma_tf32(float c[4],
    float a0, float a1, float a2, float a3, float b0, float b1)
{
    asm("mma.sync.aligned.m16n8k8.row.col.f32.tf32.tf32.f32 "
        "{%0,%1,%2,%3}, {%4,%5,%6,%7}, {%8,%9}, {%0,%1,%2,%3};"
        : "+f"(c[0]), "+f"(c[1]), "+f"(c[2]), "+f"(c[3])
        : "r"(__float_as_uint(a0)), "r"(__float_as_uint(a1)),
          "r"(__float_as_uint(a2)), "r"(__float_as_uint(a3)),
          "r"(__float_as_uint(b0)), "r"(__float_as_uint(b1)));
}

// ---------------- scratch (static device globals; no runtime allocation) ----
__device__ float gQKV[3*B*N*HID];         // Qh | Kh | Vh
__device__ float gX  [B*H*(size_t)N*N];   // x[b,h,i,j] post-mask
__device__ float gEB [B*(size_t)N*N*H];   // edge_bias2[b,i,j,h]
__device__ float gWt [B*H*(size_t)N*N];   // combined softmax weights [b,h,i,j]
__device__ float gAtt[B*N*HID];           // (x_local+x_long) flattened

// ============ GEMM body: C[2048,256] = A @ W^T + bias ======================
__device__ __forceinline__ void gemm_nt_body(
    const float* __restrict__ A, const float* __restrict__ W,
    const float* __restrict__ bias, float* __restrict__ C)
{
    constexpr int Kd = 256;
    __shared__ __align__(16) float As[16][68];
    __shared__ __align__(16) float Bs[16][68];
    const int l  = threadIdx.x;
    const int tx = l & 15, ty = l >> 4;
    const int m0 = blockIdx.y * 64, n0 = blockIdx.x * 64;
    const int lrow = l >> 2, lq = l & 3;
    ull acc2[4][2];
    #pragma unroll
    for (int i = 0; i < 4; i++) { acc2[i][0] = 0ull; acc2[i][1] = 0ull; }
    for (int k0 = 0; k0 < Kd; k0 += 16) {
        float4 a4 = *(const float4*)(A + (size_t)(m0 + lrow) * Kd + k0 + lq * 4);
        float4 b4 = *(const float4*)(W + (size_t)(n0 + lrow) * Kd + k0 + lq * 4);
        As[lq*4+0][lrow] = a4.x; As[lq*4+1][lrow] = a4.y;
        As[lq*4+2][lrow] = a4.z; As[lq*4+3][lrow] = a4.w;
        Bs[lq*4+0][lrow] = b4.x; Bs[lq*4+1][lrow] = b4.y;
        Bs[lq*4+2][lrow] = b4.z; Bs[lq*4+3][lrow] = b4.w;
        __syncthreads();
        #pragma unroll
        for (int k = 0; k < 16; k++) {
            float4 av = *(const float4*)&As[k][ty*4];
            ull b2[2];
            b2[0] = *(const ull*)&Bs[k][tx*4];
            b2[1] = *(const ull*)&Bs[k][tx*4+2];
            ull a2[4] = {dup2(av.x), dup2(av.y), dup2(av.z), dup2(av.w)};
            #pragma unroll
            for (int ii = 0; ii < 4; ii++) {
                fma2(acc2[ii][0], a2[ii], b2[0]);
                fma2(acc2[ii][1], a2[ii], b2[1]);
            }
        }
        __syncthreads();
    }
    #pragma unroll
    for (int ii = 0; ii < 4; ii++) {
        int m = m0 + ty*4 + ii;
        float2 p0 = up2(acc2[ii][0]), p1 = up2(acc2[ii][1]);
        float4 o;
        o.x = p0.x + bias[n0 + tx*4 + 0];
        o.y = p0.y + bias[n0 + tx*4 + 1];
        o.z = p1.x + bias[n0 + tx*4 + 2];
        o.w = p1.y + bias[n0 + tx*4 + 3];
        *(float4*)(C + (size_t)m * 256 + n0 + tx*4) = o;
    }
}

__global__ __launch_bounds__(256) void gemm_qkv_kernel(
    const float* q, const float* k, const float* v,
    const float* Wq, const float* Wk, const float* Wv,
    const float* bq, const float* bk, const float* bv)
{
    const int z = blockIdx.z;
    const float* A = (z == 0) ? q : (z == 1) ? k : v;
    const float* W = (z == 0) ? Wq : (z == 1) ? Wk : Wv;
    const float* bias = (z == 0) ? bq : (z == 1) ? bk : bv;
    gemm_nt_body(A, W, bias, gQKV + (size_t)z * B * N * HID);
}

__global__ __launch_bounds__(256) void gemm_out_kernel(
    const float* __restrict__ Wo, const float* __restrict__ bo, float* __restrict__ out)
{
    gemm_nt_body(gAtt, Wo, bo, out);
}

// ============ x[b,h,i,j] = mask(SCALE * Qh Kh^T) ===========================
__global__ __launch_bounds__(256) void qk_kernel(const float* __restrict__ adj,
                                                 const int* __restrict__ use_adj)
{
    __shared__ __align__(16) float Qs[32][132];
    __shared__ __align__(16) float Ks[32][132];
    const int l  = threadIdx.x;
    const int bh = blockIdx.z, b = bh >> 3, h = bh & 7;
    const int i0 = blockIdx.y * 128, j0 = blockIdx.x * 128;
    const float* Qg = gQKV + (size_t)b * N * HID + h * DK;
    const float* Kg = gQKV + (size_t)B*N*HID + (size_t)b * N * HID + h * DK;
    #pragma unroll
    for (int it = 0; it < 4; it++) {
        int e = l + it * 256;
        int row = e >> 3, q4 = e & 7;
        float4 a4 = *(const float4*)(Qg + (size_t)(i0 + row) * HID + q4 * 4);
        float4 b4 = *(const float4*)(Kg + (size_t)(j0 + row) * HID + q4 * 4);
        Qs[q4*4+0][row] = a4.x; Qs[q4*4+1][row] = a4.y;
        Qs[q4*4+2][row] = a4.z; Qs[q4*4+3][row] = a4.w;
        Ks[q4*4+0][row] = b4.x; Ks[q4*4+1][row] = b4.y;
        Ks[q4*4+2][row] = b4.z; Ks[q4*4+3][row] = b4.w;
    }
    __syncthreads();
    const int tx = l & 15, ty = l >> 4;
    ull acc2[8][4];
    #pragma unroll
    for (int i = 0; i < 8; i++)
        #pragma unroll
        for (int j = 0; j < 4; j++) acc2[i][j] = 0ull;
    #pragma unroll
    for (int k = 0; k < 32; k++) {
        float4 t0 = *(const float4*)&Qs[k][ty*8];
        float4 t1 = *(const float4*)&Qs[k][ty*8+4];
        ull a2[8] = {dup2(t0.x), dup2(t0.y), dup2(t0.z), dup2(t0.w),
                     dup2(t1.x), dup2(t1.y), dup2(t1.z), dup2(t1.w)};
        ull b2[4];
        b2[0] = *(const ull*)&Ks[k][tx*8+0];
        b2[1] = *(const ull*)&Ks[k][tx*8+2];
        b2[2] = *(const ull*)&Ks[k][tx*8+4];
        b2[3] = *(const ull*)&Ks[k][tx*8+6];
        #pragma unroll
        for (int ii = 0; ii < 8; ii++)
            #pragma unroll
            for (int jj = 0; jj < 4; jj++)
                fma2(acc2[ii][jj], a2[ii], b2[jj]);
    }
    const int ua = use_adj[0];
    #pragma unroll
    for (int ii = 0; ii < 8; ii++) {
        int i = i0 + ty*8 + ii;
        const float* adjrow = adj + ((size_t)b * N + i) * N;
        float* xrow = gX + ((size_t)bh * N + i) * N;
        #pragma unroll
        for (int j4 = 0; j4 < 2; j4++) {
            int j = j0 + tx*8 + j4*4;
            float2 pa = up2(acc2[ii][j4*2+0]);
            float2 pb = up2(acc2[ii][j4*2+1]);
            float vv[4] = {pa.x * SCALE, pa.y * SCALE, pb.x * SCALE, pb.y * SCALE};
            if (ua) {
                #pragma unroll
                for (int jj = 0; jj < 4; jj++) {
                    float a = adjrow[j + jj];
                    vv[jj] = (a > 0.f ? vv[jj] : NEGV) * a;
                }
            }
            float4 o = {vv[0], vv[1], vv[2], vv[3]};
            *(float4*)(xrow + j) = o;
        }
    }
}

// ============ fused edge kernel v10: stages A,B fma2; stage C tf32 MMA =====
__global__ __launch_bounds__(256) void edge_kernel(
    const float* __restrict__ edge_fea, const float* __restrict__ adj1,
    const float* __restrict__ Wap, const float* __restrict__ bap,
    const float* __restrict__ Wep, const float* __restrict__ bep,
    const float* __restrict__ Woe, float* __restrict__ edge_out)
{
    __shared__ __align__(16) float efs[16][514];   // 16 p-rows x (16 q * 32 e)
    __shared__ __align__(16) float WepTs[32][8];   // [e][h]  = Wep[h*32+e]
    __shared__ __align__(16) float WapTs[8][32];   // [h][e]  = Wap[e*8+h]
    __shared__ __align__(16) float WoeTs[32][32];  // [k][j]  = Woe[j*32+k]
    __shared__ __align__(16) float bapS[32];
    __shared__ float bepS[8];
    const int l = threadIdx.x;
    const int b = blockIdx.z;
    const int p0 = blockIdx.y * 16, q0 = blockIdx.x * 16;

    { int e = l >> 3, h = l & 7;  WepTs[e][h] = Wep[h*32+e]; }
    { int h = l >> 5, e = l & 31; WapTs[h][e] = Wap[e*8+h];  }
    #pragma unroll
    for (int t4 = 0; t4 < 4; t4++) {
        int idx = l + t4 * 256;
        int kk = idx >> 5, j = idx & 31;
        WoeTs[kk][j] = Woe[j*32+kk];
    }
    if (l < 32) bapS[l] = bap[l];
    if (l < 8)  bepS[l] = bep[l];

    const int lr = l >> 4, lc = l & 15;
    const float* efbase = edge_fea + (((size_t)b * N + p0 + lr) * N + q0) * E;
    #pragma unroll
    for (int k = 0; k < 8; k++) {
        int c4 = lc + k * 16;
        float4 v = *(const float4*)(efbase + c4 * 4);
        efs[lr][c4*4+0] = v.x; efs[lr][c4*4+1] = v.y;
        efs[lr][c4*4+2] = v.z; efs[lr][c4*4+3] = v.w;
    }
    __syncthreads();

    const int tp = l & 15, tq = l >> 4;
    const int p = p0 + tp, q = q0 + tq;

    ull efp[16];
    #pragma unroll
    for (int e2 = 0; e2 < 16; e2++) efp[e2] = *(const ull*)&efs[tp][tq*32 + 2*e2];

    float xh[8];
    #pragma unroll
    for (int hh = 0; hh < 8; hh++)
        xh[hh] = gX[(((size_t)b * H + hh) * N + q) * N + p];
    const float a1t = adj1[((size_t)b * N + q) * N + p];

    // ---- Stage A: gEB[b,q,p,h] = ef . Wep[h,:] + bep[h]
    ull accA[4] = {0ull, 0ull, 0ull, 0ull};
    #pragma unroll
    for (int e2 = 0; e2 < 16; e2++) {
        float2 ev = up2(efp[e2]);
        ull d0 = dup2(ev.x), d1 = dup2(ev.y);
        const ull* w0 = (const ull*)WepTs[2*e2];
        const ull* w1 = (const ull*)WepTs[2*e2+1];
        #pragma unroll
        for (int h2 = 0; h2 < 4; h2++) { fma2(accA[h2], d0, w0[h2]); fma2(accA[h2], d1, w1[h2]); }
    }
    {
        float* ebout = gEB + (((size_t)b * N + q) * N + p) * H;
        float2 r0 = up2(accA[0]), r1 = up2(accA[1]), r2 = up2(accA[2]), r3 = up2(accA[3]);
        float4 o0 = {r0.x + bepS[0], r0.y + bepS[1], r1.x + bepS[2], r1.y + bepS[3]};
        float4 o1 = {r2.x + bepS[4], r2.y + bepS[5], r3.x + bepS[6], r3.y + bepS[7]};
        *(float4*)(ebout)     = o0;
        *(float4*)(ebout + 4) = o1;
    }

    // ---- Stage B: t = ef + a1 * (x . Wap^T + bap)   (overwrites efp)
    {
        ull accB[16];
        #pragma unroll
        for (int e2 = 0; e2 < 16; e2++) accB[e2] = 0ull;
        #pragma unroll
        for (int hh = 0; hh < 8; hh++) {
            ull xd = dup2(xh[hh]);
            const ull* wp = (const ull*)WapTs[hh];
            #pragma unroll
            for (int e2 = 0; e2 < 16; e2++) fma2(accB[e2], xd, wp[e2]);
        }
        ull a1d = dup2(a1t);
        const ull* bap2 = (const ull*)bapS;
        #pragma unroll
        for (int e2 = 0; e2 < 16; e2++) {
            fma2(efp[e2], a1d, bap2[e2]);
            fma2(efp[e2], a1d, accB[e2]);
        }
    }
    // write t back to own slot; warp-local visibility is enough for stage C
    #pragma unroll
    for (int e2 = 0; e2 < 16; e2++)
        *(ull*)&efs[tp][tq*32 + 2*e2] = efp[e2];
    __syncwarp();

    // ---- Stage C: out = T @ WoeT via m16n8k8 tf32 MMA (3-term split) ------
    // pair r = l; warp w owns rows {32w..32w+31} == its own lanes' slots.
    {
        const int lane = l & 31, w = l >> 5;
        const int grp = lane >> 2, tig = lane & 3;
        #pragma unroll
        for (int mg = 0; mg < 2; mg++) {
            const int tqA = w * 2 + mg;
            const float* T0 = &efs[grp][tqA * 32];
            const float* T1 = &efs[grp + 8][tqA * 32];
            float ahi[4][4], alo[4][4];
            #pragma unroll
            for (int kt = 0; kt < 4; kt++) {
                float x0 = T0[kt*8 + tig];
                float x1 = T1[kt*8 + tig];
                float x2 = T0[kt*8 + tig + 4];
                float x3 = T1[kt*8 + tig + 4];
                ahi[kt][0] = tf32r(x0); alo[kt][0] = tf32r(x0 - ahi[kt][0]);
                ahi[kt][1] = tf32r(x1); alo[kt][1] = tf32r(x1 - ahi[kt][1]);
                ahi[kt][2] = tf32r(x2); alo[kt][2] = tf32r(x2 - ahi[kt][2]);
                ahi[kt][3] = tf32r(x3); alo[kt][3] = tf32r(x3 - ahi[kt][3]);
            }
            #pragma unroll
            for (int nt = 0; nt < 4; nt++) {
                float c[4] = {0.f, 0.f, 0.f, 0.f};
                #pragma unroll
                for (int kt = 0; kt < 4; kt++) {
                    float b0 = WoeTs[kt*8 + tig][nt*8 + grp];
                    float b1 = WoeTs[kt*8 + tig + 4][nt*8 + grp];
                    float b0h = tf32r(b0), b0l = tf32r(b0 - b0h);
                    float b1h = tf32r(b1), b1l = tf32r(b1 - b1h);
                    mma_tf32(c, ahi[kt][0], ahi[kt][1], ahi[kt][2], ahi[kt][3], b0h, b1h);
                    mma_tf32(c, alo[kt][0], alo[kt][1], alo[kt][2], alo[kt][3], b0h, b1h);
                    mma_tf32(c, ahi[kt][0], ahi[kt][1], ahi[kt][2], ahi[kt][3], b0l, b1l);
                }
                efs[grp][tqA*32 + nt*8 + 2*tig]       = c[0];
                efs[grp][tqA*32 + nt*8 + 2*tig + 1]   = c[1];
                efs[grp + 8][tqA*32 + nt*8 + 2*tig]     = c[2];
                efs[grp + 8][tqA*32 + nt*8 + 2*tig + 1] = c[3];
            }
        }
    }
    __syncthreads();
    float* eob = edge_out + (((size_t)b * N + p0 + lr) * N + q0) * E;
    #pragma unroll
    for (int k = 0; k < 8; k++) {
        int c4 = lc + k * 16;
        float4 v = {efs[lr][c4*4+0], efs[lr][c4*4+1], efs[lr][c4*4+2], efs[lr][c4*4+3]};
        *(float4*)(eob + c4 * 4) = v;
    }
}

// ============ combined softmax weights: one block per (b,i), warp = head ====
__global__ __launch_bounds__(256) void softmax_kernel(
    const float* __restrict__ attn_bias, const float* __restrict__ adj1)
{
    const int bi = blockIdx.x;
    const int b = bi >> 9, i = bi & 511;
    const int h = threadIdx.x >> 5, lane = threadIdx.x & 31;
    const size_t bh = (size_t)b * H + h;
    const float* xrow  = gX + (bh * N + i) * N;
    const float* abrow = attn_bias + (bh * N + i) * N;
    const float* ebrow = gEB + (size_t)bi * N * H + h;
    const float* a1row = adj1 + (size_t)bi * N;

    float lgG[16], lgL[16];
    float mG = -3.4e38f, mL = -3.4e38f;
    #pragma unroll
    for (int k = 0; k < 16; k++) {
        int j = lane + k * 32;
        float xv = xrow[j];
        float g  = xv * abrow[j];
        float ll = xv * ebrow[(size_t)j * H] * a1row[j];
        lgG[k] = g; lgL[k] = ll;
        mG = fmaxf(mG, g); mL = fmaxf(mL, ll);
    }
    #pragma unroll
    for (int o = 16; o > 0; o >>= 1) {
        mG = fmaxf(mG, __shfl_xor_sync(0xffffffffu, mG, o));
        mL = fmaxf(mL, __shfl_xor_sync(0xffffffffu, mL, o));
    }
    float sG = 0.f, sL = 0.f;
    #pragma unroll
    for (int k = 0; k < 16; k++) {
        float eG = __expf(lgG[k] - mG);
        float eL = __expf(lgL[k] - mL);
        lgG[k] = eG; lgL[k] = eL;
        sG += eG; sL += eL;
    }
    #pragma unroll
    for (int o = 16; o > 0; o >>= 1) {
        sG += __shfl_xor_sync(0xffffffffu, sG, o);
        sL += __shfl_xor_sync(0xffffffffu, sL, o);
    }
    const float iG = 1.f / sG, iL = 1.f / sL;
    float* wrow = gWt + (bh * N + i) * N;
    #pragma unroll
    for (int k = 0; k < 16; k++)
        wrow[lane + k * 32] = lgG[k] * iG + lgL[k] * iL;
}

// ============ AV: gAtt[b,i,h*32+d] = sum_j gWt[b,h,i,j] * Vh[b,j,h*32+d] ====
__global__ __launch_bounds__(256) void av_kernel()
{
    __shared__ __align__(16) float Ws[32][132];
    __shared__ __align__(16) float Vs[32][36];
    const int l = threadIdx.x;
    const int bh = blockIdx.y, b = bh >> 3, h = bh & 7;
    const int i0 = blockIdx.x * 128;
    const float* Wg = gWt + ((size_t)bh * N + i0) * N;
    const float* Vg = gQKV + 2*(size_t)B*N*HID + (size_t)b * N * HID + h * DK;
    const int tx = l & 15, ty = l >> 4;
    ull acc2[4][2];
    #pragma unroll
    for (int i = 0; i < 4; i++) { acc2[i][0] = 0ull; acc2[i][1] = 0ull; }
    for (int k0 = 0; k0 < N; k0 += 32) {
        #pragma unroll
        for (int it = 0; it < 4; it++) {
            int e = l + it * 256;
            int row = e >> 3, q4 = e & 7;
            float4 v = *(const float4*)(Wg + (size_t)row * N + k0 + q4 * 4);
            Ws[q4*4+0][row] = v.x; Ws[q4*4+1][row] = v.y;
            Ws[q4*4+2][row] = v.z; Ws[q4*4+3][row] = v.w;
        }
        {
            int row = l >> 3, q4 = l & 7;
            float4 v = *(const float4*)(Vg + (size_t)(k0 + row) * HID + q4 * 4);
            *(float4*)&Vs[row][q4*4] = v;
        }
        __syncthreads();
        #pragma unroll
        for (int kk = 0; kk < 32; kk++) {
            ull a2[4];
            a2[0] = *(const ull*)&Ws[kk][ty*8+0];
            a2[1] = *(const ull*)&Ws[kk][ty*8+2];
            a2[2] = *(const ull*)&Ws[kk][ty*8+4];
            a2[3] = *(const ull*)&Ws[kk][ty*8+6];
            float2 bv = *(const float2*)&Vs[kk][tx*2];
            ull bx = dup2(bv.x), by = dup2(bv.y);
            #pragma unroll
            for (int rp = 0; rp < 4; rp++) {
                fma2(acc2[rp][0], a2[rp], bx);
                fma2(acc2[rp][1], a2[rp], by);
            }
        }
        __syncthreads();
    }
    #pragma unroll
    for (int rp = 0; rp < 4; rp++) {
        float2 c0 = up2(acc2[rp][0]);
        float2 c1 = up2(acc2[rp][1]);
        float2 o0 = {c0.x, c1.x};
        float2 o1 = {c0.y, c1.y};
        *(float2*)(gAtt + ((size_t)b * N + i0 + ty*8 + 2*rp    ) * HID + h * DK + tx * 2) = o0;
        *(float2*)(gAtt + ((size_t)b * N + i0 + ty*8 + 2*rp + 1) * HID + h * DK + tx * 2) = o1;
    }
}

// ===========================================================================
extern "C" void kernel_launch(void* const* d_in, const int* in_sizes, int n_in,
                              void* d_out, int out_size)
{
    (void)in_sizes; (void)n_in; (void)out_size;
    const float* q         = (const float*)d_in[0];
    const float* k         = (const float*)d_in[1];
    const float* v         = (const float*)d_in[2];
    const float* adj       = (const float*)d_in[3];
    const float* adj1      = (const float*)d_in[4];
    const float* edge_fea  = (const float*)d_in[5];
    const float* attn_bias = (const float*)d_in[6];
    const float* Wq = (const float*)d_in[7];
    const float* bq = (const float*)d_in[8];
    const float* Wk = (const float*)d_in[9];
    const float* bk = (const float*)d_in[10];
    const float* Wv = (const float*)d_in[11];
    const float* bv = (const float*)d_in[12];
    const float* Wap = (const float*)d_in[13];
    const float* bap = (const float*)d_in[14];
    const float* Wep = (const float*)d_in[15];
    const float* bep = (const float*)d_in[16];
    const float* Wo  = (const float*)d_in[17];
    const float* bo  = (const float*)d_in[18];
    const float* Woe = (const float*)d_in[19];
    const int* use_adj = (const int*)d_in[20];

    float* out      = (float*)d_out;
    float* edge_out = out + (size_t)B * N * HID;

    gemm_qkv_kernel<<<dim3(4, 32, 3), 256>>>(q, k, v, Wq, Wk, Wv, bq, bk, bv);
    qk_kernel<<<dim3(4, 4, B * H), 256>>>(adj, use_adj);
    edge_kernel<<<dim3(N / 16, N / 16, B), 256>>>(edge_fea, adj1, Wap, bap,
                                                  Wep, bep, Woe, edge_out);
    softmax_kernel<<<B * N, 256>>>(attn_bias, adj1);
    av_kernel<<<dim3(N / 128, B * H), 256>>>();
    gemm_out_kernel<<<dim3(4, 32), 256>>>(Wo, bo, out);
}